// round 1
// baseline (speedup 1.0000x reference)
#include <cuda_runtime.h>
#include <math.h>

#define D 128
#define NSLOT 8
#define BMAX 65536
#define OUTW 1288   // 2*D + NSLOT*D + NSLOT

// scratch (static device globals; no runtime allocation)
__device__ float g_M[D * D];          // Wq^T Wk
__device__ float g_WfT[D * D];        // Wf^T
__device__ float g_U[(size_t)BMAX * D];   // state @ M
__device__ float g_S[(size_t)BMAX * D];   // softmax-weighted new_slots sum

// ---------------------------------------------------------------------------
// prep: blocks 0..127 compute M rows, blocks 128..255 transpose Wf
// ---------------------------------------------------------------------------
__global__ void prep_kernel(const float* __restrict__ Wq,
                            const float* __restrict__ Wk,
                            const float* __restrict__ Wf) {
    int d = blockIdx.x;
    int t = threadIdx.x;
    if (d < D) {
        // M[d][t] = sum_e Wq[e][d] * Wk[e][t]
        float acc = 0.f;
#pragma unroll 8
        for (int e = 0; e < D; e++)
            acc = fmaf(Wq[e * D + d], Wk[e * D + t], acc);
        g_M[d * D + t] = acc;
    } else {
        int dd = d - D;
        g_WfT[dd * D + t] = Wf[t * D + dd];
    }
}

// ---------------------------------------------------------------------------
// SGEMM: C[r][c] (+offset coff, row stride ldc) = sum_k A[r][k] * Bm[k][c]
// A: [rows x 128] row-major. Bm: [128 x 128] row-major.
// Block tile: 64 rows x 128 cols, 256 threads, 8x4 outputs per thread.
// ---------------------------------------------------------------------------
__global__ __launch_bounds__(256, 2)
void gemm_kernel(const float* __restrict__ A, const float* __restrict__ Bm,
                 float* __restrict__ C, int ldc, int coff) {
    __shared__ float As[64 * 32];
    __shared__ float Bs[32 * D];

    const int tid = threadIdx.x;
    const int tx = tid & 31;      // col group: cols tx*4 .. tx*4+3
    const int ty = tid >> 5;      // row group: rows ty*8 .. ty*8+7
    const int brow = blockIdx.x * 64;

    float acc[8][4];
#pragma unroll
    for (int i = 0; i < 8; i++)
#pragma unroll
        for (int j = 0; j < 4; j++) acc[i][j] = 0.f;

    for (int k0 = 0; k0 < D; k0 += 32) {
        // stage A tile: 64 x 32
#pragma unroll
        for (int j = 0; j < 2; j++) {
            int idx = tid + j * 256;          // 0..511
            int r = idx >> 3;                 // 0..63
            int c4 = idx & 7;                 // 0..7 (float4 within 32-wide k chunk)
            float4 v = *(const float4*)(A + (size_t)(brow + r) * D + k0 + c4 * 4);
            *(float4*)(As + r * 32 + c4 * 4) = v;
        }
        // stage B tile: 32 x 128
#pragma unroll
        for (int j = 0; j < 4; j++) {
            int idx = tid + j * 256;          // 0..1023
            int kr = idx >> 5;                // 0..31
            int c4 = idx & 31;                // 0..31
            float4 v = *(const float4*)(Bm + (size_t)(k0 + kr) * D + c4 * 4);
            *(float4*)(Bs + kr * D + c4 * 4) = v;
        }
        __syncthreads();

#pragma unroll
        for (int k = 0; k < 32; k += 4) {
            float4 b0 = *(const float4*)(Bs + (k + 0) * D + tx * 4);
            float4 b1 = *(const float4*)(Bs + (k + 1) * D + tx * 4);
            float4 b2 = *(const float4*)(Bs + (k + 2) * D + tx * 4);
            float4 b3 = *(const float4*)(Bs + (k + 3) * D + tx * 4);
#pragma unroll
            for (int i = 0; i < 8; i++) {
                float4 a = *(const float4*)(As + (ty * 8 + i) * 32 + k);
                acc[i][0] = fmaf(a.x, b0.x, acc[i][0]);
                acc[i][1] = fmaf(a.x, b0.y, acc[i][1]);
                acc[i][2] = fmaf(a.x, b0.z, acc[i][2]);
                acc[i][3] = fmaf(a.x, b0.w, acc[i][3]);
                acc[i][0] = fmaf(a.y, b1.x, acc[i][0]);
                acc[i][1] = fmaf(a.y, b1.y, acc[i][1]);
                acc[i][2] = fmaf(a.y, b1.z, acc[i][2]);
                acc[i][3] = fmaf(a.y, b1.w, acc[i][3]);
                acc[i][0] = fmaf(a.z, b2.x, acc[i][0]);
                acc[i][1] = fmaf(a.z, b2.y, acc[i][1]);
                acc[i][2] = fmaf(a.z, b2.z, acc[i][2]);
                acc[i][3] = fmaf(a.z, b2.w, acc[i][3]);
                acc[i][0] = fmaf(a.w, b3.x, acc[i][0]);
                acc[i][1] = fmaf(a.w, b3.y, acc[i][1]);
                acc[i][2] = fmaf(a.w, b3.z, acc[i][2]);
                acc[i][3] = fmaf(a.w, b3.w, acc[i][3]);
            }
        }
        __syncthreads();
    }

#pragma unroll
    for (int i = 0; i < 8; i++) {
        float4 v = make_float4(acc[i][0], acc[i][1], acc[i][2], acc[i][3]);
        *(float4*)(C + (size_t)(brow + ty * 8 + i) * ldc + coff + tx * 4) = v;
    }
}

// ---------------------------------------------------------------------------
// Elementwise per-row kernel: one block (128 threads) per batch row.
// ---------------------------------------------------------------------------
__global__ __launch_bounds__(128)
void ew_kernel(const float* __restrict__ state, const float* __restrict__ slots,
               const float* __restrict__ acts, const float* __restrict__ Wg_w,
               const float* __restrict__ Wg_b, const float* __restrict__ U,
               float* __restrict__ S, float* __restrict__ out) {
    const int b = blockIdx.x;
    const int t = threadIdx.x;
    const int lane = t & 31;
    const int w = t >> 5;

    __shared__ float st[D];
    __shared__ float us[D];
    __shared__ float sl[NSLOT * D];
    __shared__ float a_sh[NSLOT];
    __shared__ float dotu[NSLOT], dots[NSLOT], nrm[NSLOT];
    __shared__ float gpart[4];
    __shared__ float stn2_sh;

    const float sv = state[(size_t)b * D + t];
    st[t] = sv;
    us[t] = U[(size_t)b * D + t];
    {
        const float4* slv = (const float4*)(slots + (size_t)b * NSLOT * D);
        float4* dst = (float4*)sl;
        dst[t] = slv[t];
        dst[t + 128] = slv[t + 128];
    }
    if (t < NSLOT) a_sh[t] = acts[(size_t)b * NSLOT + t];
    __syncthreads();

    // decayed activations (redundant per thread, cheap)
    float na[NSLOT];
#pragma unroll
    for (int n = 0; n < NSLOT; n++) na[n] = a_sh[n] * 0.95f;

    // gate partial for this thread's dim t
    float wm = 0.f;
#pragma unroll
    for (int n = 0; n < NSLOT; n++) wm = fmaf(na[n], sl[n * D + t], wm);
    wm *= (1.0f / NSLOT);
    float gdp = fmaf(sv, Wg_w[t], wm * Wg_w[D + t]);

    // per-warp reductions: warp w owns slots n0=2w, n1=2w+1
    const int n0 = 2 * w, n1 = 2 * w + 1;
    float du0 = 0, du1 = 0, ds0 = 0, ds1 = 0, q0 = 0, q1 = 0, sn2 = 0;
#pragma unroll
    for (int i = 0; i < 4; i++) {
        int tt = lane + 32 * i;
        float s2 = st[tt], u2 = us[tt];
        float x0 = sl[n0 * D + tt], x1 = sl[n1 * D + tt];
        sn2 = fmaf(s2, s2, sn2);
        du0 = fmaf(u2, x0, du0);  du1 = fmaf(u2, x1, du1);
        ds0 = fmaf(s2, x0, ds0);  ds1 = fmaf(s2, x1, ds1);
        q0  = fmaf(x0, x0, q0);   q1  = fmaf(x1, x1, q1);
    }
#pragma unroll
    for (int o = 16; o; o >>= 1) {
        du0 += __shfl_xor_sync(0xFFFFFFFFu, du0, o);
        du1 += __shfl_xor_sync(0xFFFFFFFFu, du1, o);
        ds0 += __shfl_xor_sync(0xFFFFFFFFu, ds0, o);
        ds1 += __shfl_xor_sync(0xFFFFFFFFu, ds1, o);
        q0  += __shfl_xor_sync(0xFFFFFFFFu, q0, o);
        q1  += __shfl_xor_sync(0xFFFFFFFFu, q1, o);
        sn2 += __shfl_xor_sync(0xFFFFFFFFu, sn2, o);
        gdp += __shfl_xor_sync(0xFFFFFFFFu, gdp, o);
    }
    if (lane == 0) {
        dotu[n0] = du0; dotu[n1] = du1;
        dots[n0] = ds0; dots[n1] = ds1;
        nrm[n0] = q0;   nrm[n1] = q1;
        gpart[w] = gdp;
        if (w == 0) stn2_sh = sn2;
    }
    __syncthreads();

    // --- scalar phase (redundant across threads; all inputs in smem) ---
    const float gd = gpart[0] + gpart[1] + gpart[2] + gpart[3] + Wg_b[0];
    const float gate = 1.f / (1.f + __expf(-gd));
    const float stn = fmaxf(sqrtf(stn2_sh), 1e-12f);

    // attention softmax (over original activations-weighted logits)
    const float inv_sqrt_d = 0.08838834764831845f;  // 1/sqrt(128)
    float attn[NSLOT];
    float mx = -INFINITY;
#pragma unroll
    for (int n = 0; n < NSLOT; n++) {
        attn[n] = dotu[n] * inv_sqrt_d * a_sh[n];
        mx = fmaxf(mx, attn[n]);
    }
    float se = 0.f;
#pragma unroll
    for (int n = 0; n < NSLOT; n++) {
        attn[n] = __expf(attn[n] - mx);
        se += attn[n];
    }
    const float inv_se = 1.f / se;

    // novelty
    float simmax = -INFINITY;
#pragma unroll
    for (int n = 0; n < NSLOT; n++) {
        float m = (na[n] > 0.01f) ? 1.f : 0.f;
        float c = dots[n] / (stn * fmaxf(sqrtf(nrm[n]), 1e-12f));
        simmax = fmaxf(simmax, c * m);
    }
    const float novelty = 1.f - fminf(fmaxf(simmax, 0.f), 1.f);
    const bool do_write = (novelty > 0.3f) || (gate > 0.5f);

    // weakest slot (first minimum, strict <)
    int weakest = 0;
    float mn = na[0];
#pragma unroll
    for (int n = 1; n < NSLOT; n++)
        if (na[n] < mn) { mn = na[n]; weakest = n; }

    // new activations + summary softmax
    float swv[NSLOT];
    float swmx = -INFINITY;
#pragma unroll
    for (int n = 0; n < NSLOT; n++) {
        swv[n] = (do_write && n == weakest) ? 1.f : na[n];
        swmx = fmaxf(swmx, swv[n]);
    }
    float ssum = 0.f;
#pragma unroll
    for (int n = 0; n < NSLOT; n++) {
        swv[n] = __expf(swv[n] - swmx);
        ssum += swv[n];
    }
    const float inv_ss = 1.f / ssum;

    // --- outputs ---
    float* orow = out + (size_t)b * OUTW;
    float ro = 0.f, summed = 0.f;
#pragma unroll
    for (int n = 0; n < NSLOT; n++) {
        float x = sl[n * D + t];
        ro = fmaf(attn[n] * inv_se, x, ro);
        float v = (do_write && n == weakest) ? sv : x;
        orow[2 * D + n * D + t] = v;                 // new_slots
        summed = fmaf(swv[n] * inv_ss, v, summed);
    }
    orow[t] = ro;                                    // read_out
    S[(size_t)b * D + t] = summed;                   // input to summary GEMM
    if (t < NSLOT) {
        float v = a_sh[t] * 0.95f;
        if (do_write && t == weakest) v = 1.f;
        orow[2 * D + NSLOT * D + t] = v;             // new_acts_out
    }
}

// ---------------------------------------------------------------------------
extern "C" void kernel_launch(void* const* d_in, const int* in_sizes, int n_in,
                              void* d_out, int out_size) {
    const float* state = (const float*)d_in[0];
    const float* slots = (const float*)d_in[1];
    const float* acts  = (const float*)d_in[2];
    const float* Wq    = (const float*)d_in[3];
    const float* Wk    = (const float*)d_in[4];
    const float* Wg_w  = (const float*)d_in[5];
    const float* Wg_b  = (const float*)d_in[6];
    const float* Wf    = (const float*)d_in[7];
    float* out = (float*)d_out;

    const int B = in_sizes[0] / D;

    void *pM, *pWfT, *pU, *pS;
    cudaGetSymbolAddress(&pM, g_M);
    cudaGetSymbolAddress(&pWfT, g_WfT);
    cudaGetSymbolAddress(&pU, g_U);
    cudaGetSymbolAddress(&pS, g_S);

    prep_kernel<<<256, 128>>>(Wq, Wk, Wf);
    gemm_kernel<<<B / 64, 256>>>(state, (const float*)pM, (float*)pU, D, 0);
    ew_kernel<<<B, 128>>>(state, slots, acts, Wg_w, Wg_b,
                          (const float*)pU, (float*)pS, out);
    gemm_kernel<<<B / 64, 256>>>((const float*)pS, (const float*)pWfT, out, OUTW, D);
}